// round 8
// baseline (speedup 1.0000x reference)
#include <cuda_runtime.h>
#include <cstdint>

// Problem constants (fixed shapes for SparseLinear_40278203302401)
#define BATCH 32
#define NNODES 100000
#define MNODES 100000
#define NNZ_TOTAL 3200000

#define NBINS 296          // 2 * 148 SMs; bin = dst / NPB
#define NPB 338            // nodes per bin (296*338 = 100048 >= 100000)
#define BIN_CAP 12288      // mean 10811, sigma ~104 -> +14 sigma
#define A_CTA_E 4096       // edges per binning CTA (SMEM staging, static 48KB)
#define A_THREADS 512
#define B_THREADS 512
#define B_LIFT 24          // BIN_CAP / B_THREADS

// Scratch (device globals; no runtime allocation)
__device__ float g_xt[NNODES * BATCH];                  // x^T (N, 32), 12.8 MB
__device__ int   g_bin_fill[NBINS];                     // per-bin fill counters
__device__ int2  g_bucket[(size_t)NBINS * BIN_CAP];     // binned edges, 29.1 MB

// -------------------------------------------------------------------------
// exclusive scan of cnt[0..n) into offs (and pos), warp 0 only. Caller syncs.
// -------------------------------------------------------------------------
__device__ __forceinline__ void excl_scan_w0(const int* __restrict__ cnt,
                                             int* __restrict__ offs,
                                             int* __restrict__ pos,
                                             int n, int t) {
    if (t < 32) {
        int carry = 0;
        for (int c = 0; c < n; c += 32) {
            const int i = c + t;
            const int orig = (i < n) ? cnt[i] : 0;
            int v = orig;
            #pragma unroll
            for (int o = 1; o < 32; o <<= 1) {
                int u = __shfl_up_sync(0xffffffffu, v, o);
                if (t >= o) v += u;
            }
            const int excl = v - orig + carry;
            if (i < n) { offs[i] = excl; if (pos) pos[i] = excl; }
            carry += __shfl_sync(0xffffffffu, v, 31);
        }
    }
}

// -------------------------------------------------------------------------
// Kernel 1: transpose x (B=32, N) -> x_t (N, 32), float4 both directions.
// Block 0 also zeroes the bin fill counters.
// -------------------------------------------------------------------------
__global__ void __launch_bounds__(256)
k_transpose_x(const float* __restrict__ x, float* __restrict__ xt,
              int* __restrict__ bin_fill) {
    __shared__ float tile[32][33];
    const int n0 = blockIdx.x * 32;
    const int t  = threadIdx.x;
    const int r  = t >> 3;
    const int c4 = t & 7;

    if (blockIdx.x == 0) {
        for (int i = t; i < NBINS; i += 256) bin_fill[i] = 0;
    }

    float4 v = *(const float4*)&x[r * NNODES + n0 + c4 * 4];
    tile[r][c4 * 4 + 0] = v.x;
    tile[r][c4 * 4 + 1] = v.y;
    tile[r][c4 * 4 + 2] = v.z;
    tile[r][c4 * 4 + 3] = v.w;
    __syncthreads();

    float4 o;
    o.x = tile[c4 * 4 + 0][r];
    o.y = tile[c4 * 4 + 1][r];
    o.z = tile[c4 * 4 + 2][r];
    o.w = tile[c4 * 4 + 3][r];
    *(float4*)&xt[(n0 + r) * BATCH + c4 * 4] = o;
}

// -------------------------------------------------------------------------
// Kernel A: bin edges by coarse bin (dst / NPB) with SMEM staging so the
// global writes are contiguous per-bin bursts.
// Payload packed: .x = src | (node_local << 17)  (src < 2^17, local < 512)
// -------------------------------------------------------------------------
__global__ void __launch_bounds__(A_THREADS)
k_binA(const int* __restrict__ src, const int* __restrict__ dst,
       const float* __restrict__ val,
       int* __restrict__ bin_fill, int2* __restrict__ bucket) {
    __shared__ int2 stage[A_CTA_E];        // 32 KB
    __shared__ int  cnt[NBINS];
    __shared__ int  offs[NBINS];
    __shared__ int  pos[NBINS];
    __shared__ int  gbase[NBINS];

    const int t  = threadIdx.x;
    const int e0 = blockIdx.x * A_CTA_E;
    const int nE = min(A_CTA_E, NNZ_TOTAL - e0);

    for (int i = t; i < NBINS; i += A_THREADS) cnt[i] = 0;
    __syncthreads();

    // count
    for (int i = t; i < nE; i += A_THREADS) {
        const int d = dst[e0 + i];
        atomicAdd(&cnt[d / NPB], 1);
    }
    __syncthreads();

    excl_scan_w0(cnt, offs, pos, NBINS, t);
    __syncthreads();

    // reserve global segment space per bin
    for (int i = t; i < NBINS; i += A_THREADS) {
        gbase[i] = cnt[i] ? atomicAdd(&bin_fill[i], cnt[i]) : 0;
    }
    __syncthreads();

    // place into SMEM staging grouped by bin
    for (int i = t; i < nE; i += A_THREADS) {
        const int   d = dst[e0 + i];
        const int   s = src[e0 + i];
        const float v = val[e0 + i];
        const int b   = d / NPB;
        const int loc = d - b * NPB;
        const int r   = atomicAdd(&pos[b], 1);
        stage[r] = make_int2(s | (loc << 17), __float_as_int(v));
    }
    __syncthreads();

    // copy per-bin segments to global (contiguous bursts)
    const int warp = t >> 5, lane = t & 31;
    for (int b = warp; b < NBINS; b += (A_THREADS / 32)) {
        const int n  = cnt[b];
        const int o  = offs[b];
        const int gb = gbase[b];
        int2* __restrict__ seg = bucket + (size_t)b * BIN_CAP;
        for (int i = lane; i < n; i += 32) {
            const int gpos = gb + i;
            if (gpos < BIN_CAP) seg[gpos] = stage[o + i];
        }
    }
}

// -------------------------------------------------------------------------
// Kernel B: per bin: SMEM counting-sort by exact node, then warp-per-node
// register accumulation, fused bias + transpose + coalesced output.
// -------------------------------------------------------------------------
__global__ void __launch_bounds__(B_THREADS)
k_gatherB(const int2* __restrict__ bucket, const int* __restrict__ bin_fill,
          const float* __restrict__ xt, const float* __restrict__ bias,
          float* __restrict__ out) {
    extern __shared__ char sm[];
    int2* stage  = (int2*)sm;                        // BIN_CAP * 8 = 96 KB
    int*  ncnt   = (int*)(stage + BIN_CAP);          // NPB
    int*  noffs  = ncnt + NPB;                       // NPB
    int*  npos   = noffs + NPB;                      // NPB
    float (*tile)[33] = (float(*)[33])(npos + NPB);  // 32x33 floats

    const int b    = blockIdx.x;
    const int t    = threadIdx.x;
    const int warp = t >> 5, lane = t & 31;
    const int m0   = b * NPB;
    const int nNodes = min(NPB, MNODES - m0);
    const int E    = min(bin_fill[b], BIN_CAP);
    const int2* __restrict__ seg = bucket + (size_t)b * BIN_CAP;

    for (int i = t; i < NPB; i += B_THREADS) ncnt[i] = 0;
    __syncthreads();

    // load bin segment (coalesced) + count per node
    #pragma unroll 4
    for (int i = t; i < E; i += B_THREADS) {
        const int2 e = seg[i];
        stage[i] = e;
        atomicAdd(&ncnt[e.x >> 17], 1);
    }
    __syncthreads();

    excl_scan_w0(ncnt, noffs, npos, NPB, t);
    __syncthreads();

    // in-place permutation: lift to registers, then scatter by rank
    int2 held[B_LIFT];
    int nh = 0;
    #pragma unroll
    for (int k = 0; k < B_LIFT; k++) {
        const int i = t + k * B_THREADS;
        if (i < E) { held[k] = stage[i]; nh = k + 1; }
    }
    __syncthreads();
    #pragma unroll
    for (int k = 0; k < B_LIFT; k++) {
        if (k < nh) {
            const int loc = held[k].x >> 17;
            const int r = atomicAdd(&npos[loc], 1);
            stage[r] = held[k];
        }
    }
    __syncthreads();

    // warp-per-node accumulation; 2 nodes per warp per round (32-node tiles)
    const int NR = (NPB + 31) / 32;   // 11 rounds
    for (int r = 0; r < NR; r++) {
        #pragma unroll
        for (int half = 0; half < 2; half++) {
            const int n = r * 32 + half * 16 + warp;   // node-in-bin
            float acc = 0.0f;
            if (n < nNodes) {
                const int s0 = noffs[n];
                const int c  = ncnt[n];
                for (int base = 0; base < c; base += 32) {
                    const int take = min(32, c - base);
                    int2 e = make_int2(0, 0);
                    if (lane < take) e = stage[s0 + base + lane];
                    // 4-wide unrolled broadcast-gather for MLP
                    for (int j0 = 0; j0 < take; j0 += 4) {
                        float xs[4], vs[4];
                        #pragma unroll
                        for (int k = 0; k < 4; k++) {
                            const int j = j0 + k;
                            const int   sj = __shfl_sync(0xffffffffu, e.x, j & 31) & 0x1FFFF;
                            const float vj = __uint_as_float(
                                __shfl_sync(0xffffffffu, (unsigned)e.y, j & 31));
                            if (j < take) {
                                vs[k] = vj;
                                xs[k] = __ldg(&xt[sj * BATCH + lane]);
                            } else { vs[k] = 0.0f; xs[k] = 0.0f; }
                        }
                        acc += vs[0] * xs[0];
                        acc += vs[1] * xs[1];
                        acc += vs[2] * xs[2];
                        acc += vs[3] * xs[3];
                    }
                }
                acc += __ldg(&bias[m0 + n]);
            }
            tile[half * 16 + warp][lane] = acc;   // tile[node_in_round][batch]
        }
        __syncthreads();

        // write out: warp w writes batch rows w and w+16, columns m0+r*32+lane
        const int mcol = r * 32 + lane;
        if (m0 + mcol < MNODES && mcol < NPB) {
            out[warp        * MNODES + m0 + mcol] = tile[lane][warp];
            out[(warp + 16) * MNODES + m0 + mcol] = tile[lane][warp + 16];
        }
        __syncthreads();
    }
}

// -------------------------------------------------------------------------
// Launch
// Inputs (metadata order): x (B*N f32), indices (2*NNZ i32), values (NNZ f32),
//                          bias (M f32). Output: (B, M) f32.
// -------------------------------------------------------------------------
extern "C" void kernel_launch(void* const* d_in, const int* in_sizes, int n_in,
                              void* d_out, int out_size) {
    const float* x      = (const float*)d_in[0];
    const int*   indices= (const int*)d_in[1];
    const float* values = (const float*)d_in[2];
    const float* bias   = (const float*)d_in[3];
    float* out = (float*)d_out;

    const int* src = indices;              // row 0
    const int* dst = indices + NNZ_TOTAL;  // row 1

    float* xt;  cudaGetSymbolAddress((void**)&xt, g_xt);
    int*   bf;  cudaGetSymbolAddress((void**)&bf, g_bin_fill);
    int2*  bkt; cudaGetSymbolAddress((void**)&bkt, g_bucket);

    // dynamic SMEM for k_gatherB: 96KB staging + counts + tile
    const int smemB = BIN_CAP * sizeof(int2) + 3 * NPB * sizeof(int)
                    + 32 * 33 * sizeof(float);
    static bool attr_done = false;
    if (!attr_done) {
        cudaFuncSetAttribute(k_gatherB,
                             cudaFuncAttributeMaxDynamicSharedMemorySize, smemB);
        attr_done = true;
    }

    // 1. transpose x + zero bin counters
    k_transpose_x<<<NNODES / 32, 256>>>(x, xt, bf);

    // 2. coarse bin (coalesced staging sort)
    k_binA<<<(NNZ_TOTAL + A_CTA_E - 1) / A_CTA_E, A_THREADS>>>(src, dst, values, bf, bkt);

    // 3. per-bin exact sort + gather-accumulate + fused output
    k_gatherB<<<NBINS, B_THREADS, smemB>>>(bkt, bf, xt, bias, out);
}

// round 9
// speedup vs baseline: 2.7408x; 2.7408x over previous
#include <cuda_runtime.h>
#include <cuda_fp16.h>
#include <cstdint>

// Problem constants (fixed shapes for SparseLinear_40278203302401)
#define BATCH 32
#define NNODES 100000
#define MNODES 100000
#define NNZ_TOTAL 3200000

// Scratch: x transposed to (N, B) in fp16 (6.4 MB) and fp32 accumulator
// in (M, B) layout (12.8 MB). Both L2 resident.
__device__ __half g_xt_h[NNODES * BATCH];
__device__ float  g_yt[MNODES * BATCH];

__device__ __forceinline__ void red_add_v4(float* addr, float4 c) {
    asm volatile("red.global.add.v4.f32 [%0], {%1, %2, %3, %4};"
                 :: "l"(addr), "f"(c.x), "f"(c.y), "f"(c.z), "f"(c.w)
                 : "memory");
}

// -------------------------------------------------------------------------
// Kernel 1 (fused prep, role-split by blockIdx.x):
//  blocks [0, 3125)          : transpose x (B=32, N) -> xt_h (N, 32) fp16
//  blocks [3125, 3125+1563)  : init yt[m*32+b] = bias[m] (2x float4/thread)
// -------------------------------------------------------------------------
#define T_BLOCKS (NNODES / 32)              // 3125
#define I_BLOCKS ((MNODES * 8 + 511) / 512) // 1563 (800000 float4s, 2/thread)

__global__ void __launch_bounds__(256)
k_prep(const float* __restrict__ x, __half* __restrict__ xt,
       const float* __restrict__ bias, float4* __restrict__ yt4) {
    if (blockIdx.x < T_BLOCKS) {
        // ---- transpose + fp16 convert ----
        __shared__ float tile[32][33];
        const int n0 = blockIdx.x * 32;
        const int t  = threadIdx.x;
        const int r  = t >> 3;        // 0..31
        const int c4 = t & 7;         // 0..7

        float4 v = *(const float4*)&x[r * NNODES + n0 + c4 * 4];
        tile[r][c4 * 4 + 0] = v.x;
        tile[r][c4 * 4 + 1] = v.y;
        tile[r][c4 * 4 + 2] = v.z;
        tile[r][c4 * 4 + 3] = v.w;
        __syncthreads();

        // r = n_local, c4 = batch-quad; pack 4 halves -> 8B store
        __half2 h0 = __float22half2_rn(
            make_float2(tile[c4 * 4 + 0][r], tile[c4 * 4 + 1][r]));
        __half2 h1 = __float22half2_rn(
            make_float2(tile[c4 * 4 + 2][r], tile[c4 * 4 + 3][r]));
        __half2* dst2 = (__half2*)&xt[(n0 + r) * BATCH + c4 * 4];
        dst2[0] = h0;
        dst2[1] = h1;
    } else {
        // ---- bias init: yt4[idx] = bias[idx>>3], 2 float4s per thread ----
        const int base = (blockIdx.x - T_BLOCKS) * 512 + threadIdx.x;
        #pragma unroll
        for (int k = 0; k < 2; k++) {
            const int idx = base + k * 256;
            if (idx < MNODES * 8) {
                const float b = __ldg(&bias[idx >> 3]);
                yt4[idx] = make_float4(b, b, b, b);
            }
        }
    }
}

// -------------------------------------------------------------------------
// Kernel 2: edge scatter. 8 lanes per edge; fp16 gather (8B/lane = 64B/edge),
// fp32 math, red.v4.f32 scatter (128B/edge).
// Each warp owns 32 consecutive edges; 4 edges in flight per iteration.
// -------------------------------------------------------------------------
__global__ void __launch_bounds__(256)
k_edges(const int* __restrict__ src, const int* __restrict__ dst,
        const float* __restrict__ val,
        const __half* __restrict__ xt, float* yt) {
    const int warp_id = (blockIdx.x * blockDim.x + threadIdx.x) >> 5;
    const int lane = threadIdx.x & 31;
    const int e0 = warp_id * 32;
    if (e0 >= NNZ_TOTAL) return;

    // lane i holds edge e0+i's metadata (coalesced; NNZ % 32 == 0)
    const int   s = src[e0 + lane];
    const int   d = dst[e0 + lane];
    const float v = val[e0 + lane];

    const int g   = lane >> 3;   // edge-group 0..3
    const int sub = lane & 7;    // batch-quad 0..7

    #pragma unroll
    for (int j = 0; j < 8; j++) {
        const int srcLane = j * 4 + g;
        const int   sj = __shfl_sync(0xffffffffu, s, srcLane);
        const int   dj = __shfl_sync(0xffffffffu, d, srcLane);
        const float vj = __shfl_sync(0xffffffffu, v, srcLane);

        // 8B fp16 gather: 4 halves for batches sub*4 .. sub*4+3
        const __half2* xp = (const __half2*)&xt[sj * BATCH + sub * 4];
        const __half2 a0 = __ldg(&xp[0]);
        const __half2 a1 = __ldg(&xp[1]);
        const float2 f0 = __half22float2(a0);
        const float2 f1 = __half22float2(a1);

        float4 c;
        c.x = vj * f0.x;
        c.y = vj * f0.y;
        c.z = vj * f1.x;
        c.w = vj * f1.y;
        red_add_v4(&yt[dj * BATCH + sub * 4], c);
    }
}

// -------------------------------------------------------------------------
// Kernel 3: transpose y_t (M, 32) -> out (B=32, M), float4 both directions.
// -------------------------------------------------------------------------
__global__ void __launch_bounds__(256)
k_write_out(const float* __restrict__ yt, float* __restrict__ out) {
    __shared__ float tile[32][33];
    const int m0 = blockIdx.x * 32;
    const int t  = threadIdx.x;
    const int r  = t >> 3;        // 0..31
    const int c4 = t & 7;         // 0..7

    float4 v = *(const float4*)&yt[(m0 + r) * BATCH + c4 * 4];
    tile[c4 * 4 + 0][r] = v.x;    // tile[b][m_local]
    tile[c4 * 4 + 1][r] = v.y;
    tile[c4 * 4 + 2][r] = v.z;
    tile[c4 * 4 + 3][r] = v.w;
    __syncthreads();

    float4 o;
    o.x = tile[r][c4 * 4 + 0];
    o.y = tile[r][c4 * 4 + 1];
    o.z = tile[r][c4 * 4 + 2];
    o.w = tile[r][c4 * 4 + 3];
    *(float4*)&out[r * MNODES + m0 + c4 * 4] = o;
}

// -------------------------------------------------------------------------
// Launch
// Inputs (metadata order): x (B*N f32), indices (2*NNZ i32), values (NNZ f32),
//                          bias (M f32). Output: (B, M) f32.
// -------------------------------------------------------------------------
extern "C" void kernel_launch(void* const* d_in, const int* in_sizes, int n_in,
                              void* d_out, int out_size) {
    const float* x      = (const float*)d_in[0];
    const int*   indices= (const int*)d_in[1];
    const float* values = (const float*)d_in[2];
    const float* bias   = (const float*)d_in[3];
    float* out = (float*)d_out;

    const int* src = indices;              // row 0
    const int* dst = indices + NNZ_TOTAL;  // row 1

    __half* xt; cudaGetSymbolAddress((void**)&xt, g_xt_h);
    float*  yt; cudaGetSymbolAddress((void**)&yt, g_yt);

    // 1. fused: transpose x -> fp16 xt  +  bias-init yt
    k_prep<<<T_BLOCKS + I_BLOCKS, 256>>>(x, xt, bias, (float4*)yt);

    // 2. edge scatter: NNZ/32 warps, 8 warps per block
    const int n_warps = NNZ_TOTAL / 32;
    k_edges<<<(n_warps + 7) / 8, 256>>>(src, dst, values, xt, yt);

    // 3. write output
    k_write_out<<<MNODES / 32, 256>>>(yt, out);
}